// round 6
// baseline (speedup 1.0000x reference)
#include <cuda_runtime.h>
#include <cstdint>

// Problem constants
// x: [8, 256, 32, 32] f32      (d_in[0])
// w: [8, 36, 64] f32           (d_in[1])
// out: [8, 512, 32, 32] f32
//
// Reference reshapes the unfolded tensor xu [B, 2304, 1024] FLAT into rows of
// 2304: row r = xu_flat[r*2304 : (r+1)*2304]. So the GEMM input A [8192 x 2304]
// is literally the feature-major unfold buffer reinterpreted row-major.
//   A_flat[(b*2304 + f)*1024 + l] = unfold(b, f, l),  f = c*9 + di*3 + dj
// Column k of a row maps to circulant block (q = k>>6, s = k&63).
//   Wt[k, j=p*64+t] = w[p, q, (t-s) & 63]
// Output: C[R, j] -> out[b=R>>10, j, l=R&1023].

#define NROWS 8192
#define KDIM  2304
#define NCOLS 512
#define PER_BATCH (KDIM * 1024)   // 2,359,296 elements per batch in A

// Scratch (allowed: __device__ globals, no allocation)
__device__ __align__(16) float g_A[(size_t)NROWS * KDIM];   // 75.5 MB
__device__ __align__(16) float g_Wt[(size_t)KDIM * NCOLS];  // 4.7 MB

// ---------------------------------------------------------------------------
// Kernel 1: expand block-circulant weight into dense Wt[k][j]
//   k = q*64 + s, j = p*64 + t, Wt[k*512 + j] = w[(p*36+q)*64 + ((t-s)&63)]
// ---------------------------------------------------------------------------
__global__ void build_wt_kernel(const float* __restrict__ w) {
    int idx = blockIdx.x * blockDim.x + threadIdx.x;
    if (idx >= KDIM * NCOLS) return;
    int k = idx >> 9;        // / 512
    int j = idx & 511;
    int q = k >> 6, s = k & 63;
    int p = j >> 6, t = j & 63;
    g_Wt[idx] = w[(p * 36 + q) * 64 + ((t - s) & 63)];
}

// ---------------------------------------------------------------------------
// Kernel 2: unfold into FEATURE-MAJOR layout (the reference's flat order):
//   g_A[(b*2304 + f)*1024 + l] = xpad[b, c, y+di-1, x+dj-1]
//   f = c*9 + di*3 + dj, l = y*32 + x
// Consecutive idx -> consecutive l: coalesced stores, mostly-coalesced loads.
// ---------------------------------------------------------------------------
__global__ void im2col_kernel(const float* __restrict__ x) {
    int idx = blockIdx.x * blockDim.x + threadIdx.x;
    if (idx >= NROWS * KDIM) return;
    int b = idx / PER_BATCH;
    int r = idx - b * PER_BATCH;
    int f = r >> 10;
    int l = r & 1023;
    int y = l >> 5;
    int xx = l & 31;
    int c = f / 9;
    int kk = f - c * 9;
    int di = kk / 3;
    int dj = kk - di * 3;
    int iy = y + di - 1;
    int ix = xx + dj - 1;
    float v = 0.0f;
    if ((unsigned)iy < 32u && (unsigned)ix < 32u)
        v = x[((b * 256 + c) * 32 + iy) * 32 + ix];
    g_A[idx] = v;
}

// ---------------------------------------------------------------------------
// Kernel 3: SGEMM 8192 x 512 x 2304 with packed fma.rn.f32x2 inner product.
//   Block tile 128x128, BK=8, 256 threads, 8x8 per thread.
//   Output layout per-batch transposed: out[(b*512 + j)*1024 + l].
// ---------------------------------------------------------------------------
#define BM 128
#define BN 128
#define BK 8
#define TM 8
#define TN 8

__global__ __launch_bounds__(256, 2) void sgemm_kernel(float* __restrict__ out) {
    __shared__ __align__(16) float As[BK][BM + 4];  // +4 pad kills store conflicts
    __shared__ __align__(16) float Bs[BK][BN];

    const int tid = threadIdx.x;
    const int bx = blockIdx.x;  // j tile: 0..3
    const int by = blockIdx.y;  // row tile: 0..63

    const float* Aptr = g_A + (size_t)by * BM * KDIM;
    const float* Bptr = g_Wt + bx * BN;

    const int innerRowA = tid >> 1;          // 0..127
    const int innerColA = (tid & 1) * 4;     // 0 or 4
    const int innerRowB = tid >> 5;          // 0..7
    const int innerColB = (tid & 31) * 4;    // 0..124

    const int threadRow = (tid >> 4) * TM;   // row offset within tile
    const int threadCol = (tid & 15) * TN;   // j offset within tile

    unsigned long long accp[TM][TN / 2];
    #pragma unroll
    for (int i = 0; i < TM; i++)
        #pragma unroll
        for (int j = 0; j < TN / 2; j++)
            accp[i][j] = 0ULL;  // bitwise (0.0f, 0.0f)

    for (int k0 = 0; k0 < KDIM; k0 += BK) {
        // Load A tile [128 x 8], store transposed into As [8][128+4]
        float4 a = *(const float4*)(Aptr + (size_t)innerRowA * KDIM + k0 + innerColA);
        As[innerColA + 0][innerRowA] = a.x;
        As[innerColA + 1][innerRowA] = a.y;
        As[innerColA + 2][innerRowA] = a.z;
        As[innerColA + 3][innerRowA] = a.w;
        // Load B tile [8 x 128]
        *(float4*)(&Bs[innerRowB][innerColB]) =
            *(const float4*)(Bptr + (size_t)(k0 + innerRowB) * NCOLS + innerColB);
        __syncthreads();

        #pragma unroll
        for (int k = 0; k < BK; k++) {
            float regM[TM];
            unsigned long long regNp[TN / 2];
            #pragma unroll
            for (int i = 0; i < TM; i++)
                regM[i] = As[k][threadRow + i];
            #pragma unroll
            for (int j = 0; j < TN / 2; j++)
                regNp[j] = *(const unsigned long long*)(&Bs[k][threadCol + 2 * j]);
            #pragma unroll
            for (int i = 0; i < TM; i++) {
                unsigned long long ap;
                asm("mov.b64 %0, {%1, %1};" : "=l"(ap) : "f"(regM[i]));
                #pragma unroll
                for (int j = 0; j < TN / 2; j++) {
                    asm("fma.rn.f32x2 %0, %1, %2, %0;"
                        : "+l"(accp[i][j]) : "l"(ap), "l"(regNp[j]));
                }
            }
        }
        __syncthreads();
    }

    // Unpack accumulators
    float acc[TM][TN];
    #pragma unroll
    for (int i = 0; i < TM; i++)
        #pragma unroll
        for (int j = 0; j < TN / 2; j++) {
            float lo, hi;
            asm("mov.b64 {%0, %1}, %2;" : "=f"(lo), "=f"(hi) : "l"(accp[i][j]));
            acc[i][2 * j]     = lo;
            acc[i][2 * j + 1] = hi;
        }

    // Write out[(b*512 + j)*1024 + l]; row tiles never cross batch (1024%128==0)
    const int n0 = by * BM + threadRow;  // 8 consecutive rows handled here
    const int b  = n0 >> 10;
    const int l0 = n0 & 1023;            // multiple of 8 -> float4 aligned
    #pragma unroll
    for (int j = 0; j < TN; j++) {
        int jj = bx * BN + threadCol + j;
        float* o = out + (((size_t)(b * 512 + jj)) << 10) + l0;
        float4 v0 = make_float4(acc[0][j], acc[1][j], acc[2][j], acc[3][j]);
        float4 v1 = make_float4(acc[4][j], acc[5][j], acc[6][j], acc[7][j]);
        *(float4*)(o)     = v0;
        *(float4*)(o + 4) = v1;
    }
}

// ---------------------------------------------------------------------------
extern "C" void kernel_launch(void* const* d_in, const int* in_sizes, int n_in,
                              void* d_out, int out_size) {
    const float* x = (const float*)d_in[0];
    const float* w = (const float*)d_in[1];
    float* out = (float*)d_out;

    build_wt_kernel<<<(KDIM * NCOLS + 255) / 256, 256>>>(w);
    im2col_kernel<<<(NROWS * KDIM + 255) / 256, 256>>>(x);
    sgemm_kernel<<<dim3(NCOLS / BN, NROWS / BM), 256>>>(out);
}

// round 10
// speedup vs baseline: 2.6854x; 2.6854x over previous
#include <cuda_runtime.h>
#include <cuda_bf16.h>
#include <cstdint>

// x: [8, 256, 32, 32] f32, w: [8, 36, 64] f32, out: [8, 512, 32, 32] f32
// GEMM: C[8192 x 512] = A[8192 x 2304] * Wt[2304 x 512]
//   A_flat[(b*2304 + f)*1024 + l] = unfold(b, f, l)   (reference's flat order)
//   WtT[j, k] = w[p, q, (t-s)&63], j=p*64+t, k=q*64+s   (stored [j][k] = B^T)
//   C[R, j] -> out[b=R>>10, j, l=R&1023]
// Precision: fp32 = hi(bf16) + lo(bf16); a*b ~= ah*bh + ah*bl + al*bh (3 MMAs)
// NOTE: tcgen05 is NOT available (harness compiles PTX for plain sm_103).
// Tensor cores reached via mma.sync.m16n8k16.bf16 (sm_80 baseline feature).

#define NROWS 8192
#define KDIM  2304
#define NCOLS 512
#define PER_BATCH (KDIM * 1024)

// Scratch
__device__ __align__(16) __nv_bfloat16 g_Ah[(size_t)NROWS * KDIM];
__device__ __align__(16) __nv_bfloat16 g_Al[(size_t)NROWS * KDIM];
__device__ __align__(16) __nv_bfloat16 g_Bh[(size_t)NCOLS * KDIM];  // [j][k]
__device__ __align__(16) __nv_bfloat16 g_Bl[(size_t)NCOLS * KDIM];

// ---------------------------------------------------------------------------
// Kernel 1: circulant weight expansion -> bf16 hi/lo, transposed [j][k]
// ---------------------------------------------------------------------------
__global__ void build_wt_kernel(const float* __restrict__ w) {
    __shared__ float ws[64];
    int pq = blockIdx.x;
    int t0 = threadIdx.x;
    if (t0 < 64) ws[t0] = w[pq * 64 + t0];
    __syncthreads();
    int p = pq / 36, q = pq - p * 36;
    #pragma unroll
    for (int m = 0; m < 8; m++) {
        int e2 = (m * 256 + t0) * 2;      // 0..4094, step 2
        int tt = e2 >> 6, s = e2 & 63;    // s even
        float v0 = ws[(tt - s) & 63];
        float v1 = ws[(tt - s - 1) & 63];
        __nv_bfloat16 h0 = __float2bfloat16(v0), h1 = __float2bfloat16(v1);
        float r0 = v0 - __bfloat162float(h0);
        float r1 = v1 - __bfloat162float(h1);
        __nv_bfloat16 l0 = __float2bfloat16(r0), l1 = __float2bfloat16(r1);
        uint32_t hp = (uint32_t)__bfloat16_as_ushort(h0) |
                      ((uint32_t)__bfloat16_as_ushort(h1) << 16);
        uint32_t lp = (uint32_t)__bfloat16_as_ushort(l0) |
                      ((uint32_t)__bfloat16_as_ushort(l1) << 16);
        size_t off = (size_t)(p * 64 + tt) * KDIM + q * 64 + s;
        *(uint32_t*)(g_Bh + off) = hp;
        *(uint32_t*)(g_Bl + off) = lp;
    }
}

// ---------------------------------------------------------------------------
// Kernel 2: im2col (feature-major flat order) -> bf16 hi/lo split
// ---------------------------------------------------------------------------
__global__ void im2col_kernel(const float* __restrict__ x) {
    int g = blockIdx.x * blockDim.x + threadIdx.x;
    size_t idx0 = (size_t)g * 4;
    if (idx0 >= (size_t)NROWS * KDIM) return;
    int b = (int)(idx0 / PER_BATCH);
    int r = (int)(idx0 - (size_t)b * PER_BATCH);
    int f = r >> 10;
    int l = r & 1023;         // multiple of 4
    int y = l >> 5, x0 = l & 31;
    int c = f / 9;
    int kk = f - c * 9;
    int di = kk / 3;
    int dj = kk - di * 3;
    int iy = y + di - 1;
    const float* src = x + (((size_t)(b * 256 + c) * 32 + iy) << 5);
    uint32_t hw[2], lw[2];
    #pragma unroll
    for (int pair = 0; pair < 2; pair++) {
        __nv_bfloat16 h[2], lo[2];
        #pragma unroll
        for (int e = 0; e < 2; e++) {
            int ix = x0 + pair * 2 + e + dj - 1;
            float v = 0.0f;
            if ((unsigned)iy < 32u && (unsigned)ix < 32u) v = src[ix];
            h[e] = __float2bfloat16(v);
            lo[e] = __float2bfloat16(v - __bfloat162float(h[e]));
        }
        hw[pair] = (uint32_t)__bfloat16_as_ushort(h[0]) |
                   ((uint32_t)__bfloat16_as_ushort(h[1]) << 16);
        lw[pair] = (uint32_t)__bfloat16_as_ushort(lo[0]) |
                   ((uint32_t)__bfloat16_as_ushort(lo[1]) << 16);
    }
    *(uint2*)(g_Ah + idx0) = make_uint2(hw[0], hw[1]);
    *(uint2*)(g_Al + idx0) = make_uint2(lw[0], lw[1]);
}

// ---------------------------------------------------------------------------
// Kernel 3: bf16 mma.sync GEMM. CTA 128x256, 512 threads (16 warps, 64x32 warp
// tile), k-chunk 32, 3-stage cp.async pipeline. 3-term split, fp32 accum.
// ---------------------------------------------------------------------------
#define KCH 32
#define NCK (KDIM / KCH)      // 72
#define LDS_STRIDE 40         // 32 + 8 pad (80B rows -> ldmatrix conflict-free)
#define SA (128 * LDS_STRIDE) // 5120 elems per A stage
#define SB (256 * LDS_STRIDE) // 10240 elems per B stage
#define OFF_AH 0
#define OFF_AL (3 * SA)             // 15360
#define OFF_BH (6 * SA)             // 30720
#define OFF_BL (6 * SA + 3 * SB)    // 61440
#define SMEM_ELEMS (6 * SA + 6 * SB)  // 92160 elems
#define SMEM_BYTES (SMEM_ELEMS * 2)   // 184320 B

__device__ __forceinline__ uint32_t smem_u32(const void* p) {
    uint32_t a;
    asm("{ .reg .u64 t; cvta.to.shared.u64 t, %1; cvt.u32.u64 %0, t; }"
        : "=r"(a) : "l"(p));
    return a;
}
__device__ __forceinline__ void cpa16(uint32_t s, const void* g) {
    asm volatile("cp.async.cg.shared.global [%0], [%1], 16;" :: "r"(s), "l"(g));
}
#define CP_COMMIT()  asm volatile("cp.async.commit_group;" ::: "memory")
#define CP_WAIT(n)   asm volatile("cp.async.wait_group %0;" :: "n"(n) : "memory")

#define LDSM4(r0, r1, r2, r3, addr) \
    asm volatile("ldmatrix.sync.aligned.m8n8.x4.shared.b16 {%0,%1,%2,%3}, [%4];" \
                 : "=r"(r0), "=r"(r1), "=r"(r2), "=r"(r3) : "r"(addr))

#define MMA16816(d, a, b) \
    asm volatile("mma.sync.aligned.m16n8k16.row.col.f32.bf16.bf16.f32 " \
                 "{%0,%1,%2,%3}, {%4,%5,%6,%7}, {%8,%9}, {%0,%1,%2,%3};" \
                 : "+f"((d)[0]), "+f"((d)[1]), "+f"((d)[2]), "+f"((d)[3]) \
                 : "r"((a)[0]), "r"((a)[1]), "r"((a)[2]), "r"((a)[3]), \
                   "r"((b)[0]), "r"((b)[1]))

__global__ __launch_bounds__(512, 1) void gemm_kernel(float* __restrict__ out) {
    extern __shared__ __align__(16) __nv_bfloat16 sm[];
    const uint32_t sbase = smem_u32(sm);
    const int tid  = threadIdx.x;
    const int lane = tid & 31;
    const int wid  = tid >> 5;
    const int wm   = wid & 1;        // 2 m-groups of 64
    const int wn   = wid >> 1;       // 8 n-groups of 32
    const int bx   = blockIdx.x;     // 0..1 (256 cols)
    const int by   = blockIdx.y;     // 0..63 (128 rows)

    const __nv_bfloat16* Ah = g_Ah + (size_t)(by * 128) * KDIM;
    const __nv_bfloat16* Al = g_Al + (size_t)(by * 128) * KDIM;
    const __nv_bfloat16* Bh = g_Bh + (size_t)(bx * 256) * KDIM;
    const __nv_bfloat16* Bl = g_Bl + (size_t)(bx * 256) * KDIM;

    // Per-thread load slots
    const int arow = tid >> 2, ac = tid & 3;              // A: 512 16B segs
    const size_t a_goff = (size_t)arow * KDIM + ac * 8;
    const uint32_t a_soff = (arow * LDS_STRIDE + ac * 8) * 2;
    const int brow0 = tid >> 2, bc = tid & 3;             // B: 1024 segs, 2/thread
    const size_t b_goff0 = (size_t)brow0 * KDIM + bc * 8;
    const size_t b_goff1 = (size_t)(brow0 + 128) * KDIM + bc * 8;
    const uint32_t b_soff0 = (brow0 * LDS_STRIDE + bc * 8) * 2;
    const uint32_t b_soff1 = ((brow0 + 128) * LDS_STRIDE + bc * 8) * 2;

    float acc[4][4][4];
    #pragma unroll
    for (int i = 0; i < 4; i++)
        #pragma unroll
        for (int j = 0; j < 4; j++)
            #pragma unroll
            for (int e = 0; e < 4; e++) acc[i][j][e] = 0.0f;

    // ldmatrix source addresses (per k16 half h, computed from these bases)
    const int a_lrow = (lane & 15);
    const int a_lcol = ((lane >> 4) & 1) * 8;
    const int b_lrow = ((lane >> 4) & 1) * 8 + (lane & 7);
    const int b_lcol = ((lane >> 3) & 1) * 8;

    auto load_chunk = [&](int ck, int stage) {
        const int k0 = ck * KCH;
        uint32_t s_ah = sbase + (OFF_AH + stage * SA) * 2 + a_soff;
        uint32_t s_al = sbase + (OFF_AL + stage * SA) * 2 + a_soff;
        cpa16(s_ah, Ah + a_goff + k0);
        cpa16(s_al, Al + a_goff + k0);
        uint32_t s_bh0 = sbase + (OFF_BH + stage * SB) * 2 + b_soff0;
        uint32_t s_bh1 = sbase + (OFF_BH + stage * SB) * 2 + b_soff1;
        uint32_t s_bl0 = sbase + (OFF_BL + stage * SB) * 2 + b_soff0;
        uint32_t s_bl1 = sbase + (OFF_BL + stage * SB) * 2 + b_soff1;
        cpa16(s_bh0, Bh + b_goff0 + k0);
        cpa16(s_bh1, Bh + b_goff1 + k0);
        cpa16(s_bl0, Bl + b_goff0 + k0);
        cpa16(s_bl1, Bl + b_goff1 + k0);
    };

    load_chunk(0, 0); CP_COMMIT();
    load_chunk(1, 1); CP_COMMIT();

    for (int ck = 0; ck < NCK; ck++) {
        const int stage = ck % 3;
        if (ck == NCK - 1) { CP_WAIT(0); } else { CP_WAIT(1); }
        __syncthreads();
        if (ck + 2 < NCK) { load_chunk(ck + 2, (ck + 2) % 3); CP_COMMIT(); }

        const uint32_t ah_base = sbase + (OFF_AH + stage * SA) * 2;
        const uint32_t al_base = sbase + (OFF_AL + stage * SA) * 2;
        const uint32_t bh_base = sbase + (OFF_BH + stage * SB) * 2;
        const uint32_t bl_base = sbase + (OFF_BL + stage * SB) * 2;

        #pragma unroll
        for (int h = 0; h < 2; h++) {
            uint32_t ahr[4][4], alr[4][4], bhr[4][2], blr[4][2];
            #pragma unroll
            for (int mt = 0; mt < 4; mt++) {
                uint32_t off = ((wm * 64 + mt * 16 + a_lrow) * LDS_STRIDE
                                + h * 16 + a_lcol) * 2;
                LDSM4(ahr[mt][0], ahr[mt][1], ahr[mt][2], ahr[mt][3], ah_base + off);
                LDSM4(alr[mt][0], alr[mt][1], alr[mt][2], alr[mt][3], al_base + off);
            }
            #pragma unroll
            for (int nt2 = 0; nt2 < 2; nt2++) {
                uint32_t off = ((wn * 32 + nt2 * 16 + b_lrow) * LDS_STRIDE
                                + h * 16 + b_lcol) * 2;
                uint32_t r0, r1, r2, r3;
                LDSM4(r0, r1, r2, r3, bh_base + off);
                bhr[nt2 * 2][0] = r0; bhr[nt2 * 2][1] = r1;
                bhr[nt2 * 2 + 1][0] = r2; bhr[nt2 * 2 + 1][1] = r3;
                LDSM4(r0, r1, r2, r3, bl_base + off);
                blr[nt2 * 2][0] = r0; blr[nt2 * 2][1] = r1;
                blr[nt2 * 2 + 1][0] = r2; blr[nt2 * 2 + 1][1] = r3;
            }
            #pragma unroll
            for (int mt = 0; mt < 4; mt++)
                #pragma unroll
                for (int nt = 0; nt < 4; nt++) {
                    MMA16816(acc[mt][nt], ahr[mt], bhr[nt]);
                    MMA16816(acc[mt][nt], ahr[mt], blr[nt]);
                    MMA16816(acc[mt][nt], alr[mt], bhr[nt]);
                }
        }
    }

    // Epilogue: C[R, j] -> out[(b*512 + j)*1024 + (R & 1023)]
    const int b     = by >> 3;
    const int lbase = (by & 7) * 128;
    #pragma unroll
    for (int mt = 0; mt < 4; mt++) {
        const int r0 = wm * 64 + mt * 16 + (lane >> 2);
        #pragma unroll
        for (int nt = 0; nt < 4; nt++) {
            const int j0 = bx * 256 + wn * 32 + nt * 8 + 2 * (lane & 3);
            float* o0 = out + (((size_t)(b * 512 + j0)) << 10) + lbase;
            float* o1 = out + (((size_t)(b * 512 + j0 + 1)) << 10) + lbase;
            o0[r0]     = acc[mt][nt][0];
            o1[r0]     = acc[mt][nt][1];
            o0[r0 + 8] = acc[mt][nt][2];
            o1[r0 + 8] = acc[mt][nt][3];
        }
    }
}

// ---------------------------------------------------------------------------
extern "C" void kernel_launch(void* const* d_in, const int* in_sizes, int n_in,
                              void* d_out, int out_size) {
    const float* x = (const float*)d_in[0];
    const float* w = (const float*)d_in[1];
    float* out = (float*)d_out;

    cudaFuncSetAttribute(gemm_kernel,
                         cudaFuncAttributeMaxDynamicSharedMemorySize, SMEM_BYTES);

    build_wt_kernel<<<288, 256>>>(w);
    im2col_kernel<<<(NROWS * KDIM / 4 + 255) / 256, 256>>>(x);
    gemm_kernel<<<dim3(2, 64), 512, SMEM_BYTES>>>(out);
}

// round 11
// speedup vs baseline: 3.7169x; 1.3841x over previous
#include <cuda_runtime.h>
#include <cuda_fp16.h>
#include <cstdint>

// x: [8, 256, 32, 32] f32, w: [8, 36, 64] f32, out: [8, 512, 32, 32] f32
// GEMM: C[8192 x 512] = A[8192 x 2304] * Wt[2304 x 512]
//   A_flat[(b*2304 + f)*1024 + l] = unfold(b, f, l)   (reference's flat order)
//   WtT[j, k] = w[p, q, (t-s)&63], j=p*64+t, k=q*64+s   (stored [j][k] = B^T)
//   C[R, j] -> out[b=R>>10, j, l=R&1023]
// Precision: A ~= ah (fp16), B = bh + bl (fp16 split). C ~= ah*bh + ah*bl.
// Dropped al*b ~ 2^-12 relative -> rel_err ~2e-4 < 1e-3.
// NOTE: tcgen05 unavailable (harness emits plain sm_103 PTX); tensor cores via
// mma.sync.m16n8k16.f16 (sm_80 baseline).

#define NROWS 8192
#define KDIM  2304
#define NCOLS 512
#define PER_BATCH (KDIM * 1024)

// Scratch
__device__ __align__(16) __half g_Ah[(size_t)NROWS * KDIM];   // 37.7 MB
__device__ __align__(16) __half g_Bh[(size_t)NCOLS * KDIM];   // [j][k]
__device__ __align__(16) __half g_Bl[(size_t)NCOLS * KDIM];

// ---------------------------------------------------------------------------
// Kernel 1: circulant weight expansion -> fp16 hi/lo, transposed [j][k]
// ---------------------------------------------------------------------------
__global__ void build_wt_kernel(const float* __restrict__ w) {
    __shared__ float ws[64];
    int pq = blockIdx.x;
    int t0 = threadIdx.x;
    if (t0 < 64) ws[t0] = w[pq * 64 + t0];
    __syncthreads();
    int p = pq / 36, q = pq - p * 36;
    #pragma unroll
    for (int m = 0; m < 8; m++) {
        int e2 = (m * 256 + t0) * 2;      // 0..4094, step 2
        int tt = e2 >> 6, s = e2 & 63;    // s even
        float v0 = ws[(tt - s) & 63];
        float v1 = ws[(tt - s - 1) & 63];
        __half h0 = __float2half_rn(v0), h1 = __float2half_rn(v1);
        __half l0 = __float2half_rn(v0 - __half2float(h0));
        __half l1 = __float2half_rn(v1 - __half2float(h1));
        uint32_t hp = (uint32_t)__half_as_ushort(h0) |
                      ((uint32_t)__half_as_ushort(h1) << 16);
        uint32_t lp = (uint32_t)__half_as_ushort(l0) |
                      ((uint32_t)__half_as_ushort(l1) << 16);
        size_t off = (size_t)(p * 64 + tt) * KDIM + q * 64 + s;
        *(uint32_t*)(g_Bh + off) = hp;
        *(uint32_t*)(g_Bl + off) = lp;
    }
}

// ---------------------------------------------------------------------------
// Kernel 2: im2col (feature-major flat order) -> single fp16 stream
// ---------------------------------------------------------------------------
__global__ void im2col_kernel(const float* __restrict__ x) {
    int g = blockIdx.x * blockDim.x + threadIdx.x;
    size_t idx0 = (size_t)g * 4;
    if (idx0 >= (size_t)NROWS * KDIM) return;
    int b = (int)(idx0 / PER_BATCH);
    int r = (int)(idx0 - (size_t)b * PER_BATCH);
    int f = r >> 10;
    int l = r & 1023;         // multiple of 4
    int y = l >> 5, x0 = l & 31;
    int c = f / 9;
    int kk = f - c * 9;
    int di = kk / 3;
    int dj = kk - di * 3;
    int iy = y + di - 1;
    const float* src = x + (((size_t)(b * 256 + c) * 32 + iy) << 5);
    uint32_t hw[2];
    #pragma unroll
    for (int pair = 0; pair < 2; pair++) {
        __half h[2];
        #pragma unroll
        for (int e = 0; e < 2; e++) {
            int ix = x0 + pair * 2 + e + dj - 1;
            float v = 0.0f;
            if ((unsigned)iy < 32u && (unsigned)ix < 32u) v = src[ix];
            h[e] = __float2half_rn(v);
        }
        hw[pair] = (uint32_t)__half_as_ushort(h[0]) |
                   ((uint32_t)__half_as_ushort(h[1]) << 16);
    }
    *(uint2*)(g_Ah + idx0) = make_uint2(hw[0], hw[1]);
}

// ---------------------------------------------------------------------------
// Kernel 3: fp16 mma.sync GEMM. CTA 128x256, 512 threads (16 warps, 64x32 warp
// tile), k-chunk 32, 4-stage cp.async pipeline. 2-term split, fp32 accum.
// ---------------------------------------------------------------------------
#define KCH 32
#define NCK (KDIM / KCH)      // 72
#define NSTG 4
#define LDS_STRIDE 40         // 32 + 8 pad (80B rows -> ldmatrix conflict-free)
#define SA (128 * LDS_STRIDE) // 5120 elems per A stage
#define SB (256 * LDS_STRIDE) // 10240 elems per B stage
#define OFF_AH 0
#define OFF_BH (NSTG * SA)              // 20480
#define OFF_BL (NSTG * (SA + SB))       // 61440
#define SMEM_ELEMS (NSTG * (SA + 2 * SB))  // 102400 elems
#define SMEM_BYTES (SMEM_ELEMS * 2)        // 204800 B

__device__ __forceinline__ uint32_t smem_u32(const void* p) {
    uint32_t a;
    asm("{ .reg .u64 t; cvta.to.shared.u64 t, %1; cvt.u32.u64 %0, t; }"
        : "=r"(a) : "l"(p));
    return a;
}
__device__ __forceinline__ void cpa16(uint32_t s, const void* g) {
    asm volatile("cp.async.cg.shared.global [%0], [%1], 16;" :: "r"(s), "l"(g));
}
#define CP_COMMIT()  asm volatile("cp.async.commit_group;" ::: "memory")
#define CP_WAIT(n)   asm volatile("cp.async.wait_group %0;" :: "n"(n) : "memory")

#define LDSM4(r0, r1, r2, r3, addr) \
    asm volatile("ldmatrix.sync.aligned.m8n8.x4.shared.b16 {%0,%1,%2,%3}, [%4];" \
                 : "=r"(r0), "=r"(r1), "=r"(r2), "=r"(r3) : "r"(addr))

#define MMA16816(d, a, b) \
    asm volatile("mma.sync.aligned.m16n8k16.row.col.f32.f16.f16.f32 " \
                 "{%0,%1,%2,%3}, {%4,%5,%6,%7}, {%8,%9}, {%0,%1,%2,%3};" \
                 : "+f"((d)[0]), "+f"((d)[1]), "+f"((d)[2]), "+f"((d)[3]) \
                 : "r"((a)[0]), "r"((a)[1]), "r"((a)[2]), "r"((a)[3]), \
                   "r"((b)[0]), "r"((b)[1]))

__global__ __launch_bounds__(512, 1) void gemm_kernel(float* __restrict__ out) {
    extern __shared__ __align__(16) __half sm[];
    const uint32_t sbase = smem_u32(sm);
    const int tid  = threadIdx.x;
    const int lane = tid & 31;
    const int wid  = tid >> 5;
    const int wm   = wid & 1;        // 2 m-groups of 64
    const int wn   = wid >> 1;       // 8 n-groups of 32
    const int bx   = blockIdx.x;     // 0..1 (256 cols)
    const int by   = blockIdx.y;     // 0..63 (128 rows)

    const __half* Ah = g_Ah + (size_t)(by * 128) * KDIM;
    const __half* Bh = g_Bh + (size_t)(bx * 256) * KDIM;
    const __half* Bl = g_Bl + (size_t)(bx * 256) * KDIM;

    // Per-thread load slots
    const int arow = tid >> 2, ac = tid & 3;              // A: 512 16B segs
    const size_t a_goff = (size_t)arow * KDIM + ac * 8;
    const uint32_t a_soff = (arow * LDS_STRIDE + ac * 8) * 2;
    const int brow0 = tid >> 2, bc = tid & 3;             // B: 1024 segs, 2/thread
    const size_t b_goff0 = (size_t)brow0 * KDIM + bc * 8;
    const size_t b_goff1 = (size_t)(brow0 + 128) * KDIM + bc * 8;
    const uint32_t b_soff0 = (brow0 * LDS_STRIDE + bc * 8) * 2;
    const uint32_t b_soff1 = ((brow0 + 128) * LDS_STRIDE + bc * 8) * 2;

    float acc[4][4][4];
    #pragma unroll
    for (int i = 0; i < 4; i++)
        #pragma unroll
        for (int j = 0; j < 4; j++)
            #pragma unroll
            for (int e = 0; e < 4; e++) acc[i][j][e] = 0.0f;

    const int a_lrow = (lane & 15);
    const int a_lcol = ((lane >> 4) & 1) * 8;
    const int b_lrow = ((lane >> 4) & 1) * 8 + (lane & 7);
    const int b_lcol = ((lane >> 3) & 1) * 8;

    auto load_chunk = [&](int ck, int stage) {
        const int k0 = ck * KCH;
        cpa16(sbase + (OFF_AH + stage * SA) * 2 + a_soff, Ah + a_goff + k0);
        uint32_t sh = sbase + (OFF_BH + stage * SB) * 2;
        uint32_t sl = sbase + (OFF_BL + stage * SB) * 2;
        cpa16(sh + b_soff0, Bh + b_goff0 + k0);
        cpa16(sh + b_soff1, Bh + b_goff1 + k0);
        cpa16(sl + b_soff0, Bl + b_goff0 + k0);
        cpa16(sl + b_soff1, Bl + b_goff1 + k0);
    };

    load_chunk(0, 0); CP_COMMIT();
    load_chunk(1, 1); CP_COMMIT();
    load_chunk(2, 2); CP_COMMIT();

    for (int ck = 0; ck < NCK; ck++) {
        const int stage = ck & 3;
        if (ck < NCK - 2)       { CP_WAIT(2); }
        else if (ck == NCK - 2) { CP_WAIT(1); }
        else                    { CP_WAIT(0); }
        __syncthreads();
        if (ck + 3 < NCK) { load_chunk(ck + 3, (ck + 3) & 3); CP_COMMIT(); }

        const uint32_t ah_base = sbase + (OFF_AH + stage * SA) * 2;
        const uint32_t bh_base = sbase + (OFF_BH + stage * SB) * 2;
        const uint32_t bl_base = sbase + (OFF_BL + stage * SB) * 2;

        #pragma unroll
        for (int h = 0; h < 2; h++) {
            uint32_t ahr[4][4], bhr[4][2], blr[4][2];
            #pragma unroll
            for (int mt = 0; mt < 4; mt++) {
                uint32_t off = ((wm * 64 + mt * 16 + a_lrow) * LDS_STRIDE
                                + h * 16 + a_lcol) * 2;
                LDSM4(ahr[mt][0], ahr[mt][1], ahr[mt][2], ahr[mt][3], ah_base + off);
            }
            #pragma unroll
            for (int nt2 = 0; nt2 < 2; nt2++) {
                uint32_t off = ((wn * 32 + nt2 * 16 + b_lrow) * LDS_STRIDE
                                + h * 16 + b_lcol) * 2;
                uint32_t r0, r1, r2, r3;
                LDSM4(r0, r1, r2, r3, bh_base + off);
                bhr[nt2 * 2][0] = r0; bhr[nt2 * 2][1] = r1;
                bhr[nt2 * 2 + 1][0] = r2; bhr[nt2 * 2 + 1][1] = r3;
                LDSM4(r0, r1, r2, r3, bl_base + off);
                blr[nt2 * 2][0] = r0; blr[nt2 * 2][1] = r1;
                blr[nt2 * 2 + 1][0] = r2; blr[nt2 * 2 + 1][1] = r3;
            }
            #pragma unroll
            for (int mt = 0; mt < 4; mt++)
                #pragma unroll
                for (int nt = 0; nt < 4; nt++) {
                    MMA16816(acc[mt][nt], ahr[mt], bhr[nt]);
                    MMA16816(acc[mt][nt], ahr[mt], blr[nt]);
                }
        }
    }

    // Epilogue: C[R, j] -> out[(b*512 + j)*1024 + (R & 1023)]
    const int b     = by >> 3;
    const int lbase = (by & 7) * 128;
    #pragma unroll
    for (int mt = 0; mt < 4; mt++) {
        const int r0 = wm * 64 + mt * 16 + (lane >> 2);
        #pragma unroll
        for (int nt = 0; nt < 4; nt++) {
            const int j0 = bx * 256 + wn * 32 + nt * 8 + 2 * (lane & 3);
            float* o0 = out + (((size_t)(b * 512 + j0)) << 10) + lbase;
            float* o1 = out + (((size_t)(b * 512 + j0 + 1)) << 10) + lbase;
            o0[r0]     = acc[mt][nt][0];
            o1[r0]     = acc[mt][nt][1];
            o0[r0 + 8] = acc[mt][nt][2];
            o1[r0 + 8] = acc[mt][nt][3];
        }
    }
}

// Marker: shifts the ncu capture slot so the GEMM (or this no-op) gets
// profiled instead of build_wt. Costs ~1us.
__global__ void marker_kernel() {}

// ---------------------------------------------------------------------------
extern "C" void kernel_launch(void* const* d_in, const int* in_sizes, int n_in,
                              void* d_out, int out_size) {
    const float* x = (const float*)d_in[0];
    const float* w = (const float*)d_in[1];
    float* out = (float*)d_out;

    cudaFuncSetAttribute(gemm_kernel,
                         cudaFuncAttributeMaxDynamicSharedMemorySize, SMEM_BYTES);

    build_wt_kernel<<<288, 256>>>(w);
    im2col_kernel<<<(NROWS * KDIM / 4 + 255) / 256, 256>>>(x);
    gemm_kernel<<<dim3(2, 64), 512, SMEM_BYTES>>>(out);
    marker_kernel<<<1, 32>>>();
}

// round 12
// speedup vs baseline: 5.7456x; 1.5458x over previous
#include <cuda_runtime.h>
#include <cuda_fp16.h>
#include <cstdint>

// x: [8, 256, 32, 32] f32, w: [8, 36, 64] f32, out: [8, 512, 32, 32] f32
// GEMM: C[8192 x 512] = A[8192 x 2304] * Wt[2304 x 512]
//   A_flat[(b*2304 + f)*1024 + l] = unfold(b, f, l)   (reference's flat order)
//   WtT[j, k] = w[p, q, (t-s)&63], j=p*64+t, k=q*64+s   (stored [j][k] = B^T)
//   C[R, j] -> out[b=R>>10, j, l=R&1023]
// Precision: plain fp16 operands, fp32 accumulate. Dropped residual terms
// contribute ~2.1e-4 each (measured R11) -> predicted rel_err ~3e-4 < 1e-3.
// NOTE: tcgen05 unavailable (harness emits plain sm_103 PTX); tensor cores via
// mma.sync.m16n8k16.f16 (sm_80 baseline).

#define NROWS 8192
#define KDIM  2304
#define NCOLS 512
#define PER_BATCH (KDIM * 1024)

// Scratch
__device__ __align__(16) __half g_Ah[(size_t)NROWS * KDIM];   // 37.7 MB
__device__ __align__(16) __half g_Bh[(size_t)NCOLS * KDIM];   // [j][k], 2.36 MB

// ---------------------------------------------------------------------------
// Kernel 1: circulant weight expansion -> fp16, transposed [j][k]
// ---------------------------------------------------------------------------
__global__ void build_wt_kernel(const float* __restrict__ w) {
    __shared__ float ws[64];
    int pq = blockIdx.x;
    int t0 = threadIdx.x;
    if (t0 < 64) ws[t0] = w[pq * 64 + t0];
    __syncthreads();
    int p = pq / 36, q = pq - p * 36;
    #pragma unroll
    for (int m = 0; m < 8; m++) {
        int e2 = (m * 256 + t0) * 2;      // 0..4094, step 2
        int tt = e2 >> 6, s = e2 & 63;    // s even
        float v0 = ws[(tt - s) & 63];
        float v1 = ws[(tt - s - 1) & 63];
        uint32_t hp = (uint32_t)__half_as_ushort(__float2half_rn(v0)) |
                      ((uint32_t)__half_as_ushort(__float2half_rn(v1)) << 16);
        size_t off = (size_t)(p * 64 + tt) * KDIM + q * 64 + s;
        *(uint32_t*)(g_Bh + off) = hp;
    }
}

// ---------------------------------------------------------------------------
// Kernel 2: im2col (feature-major flat order) -> fp16
// ---------------------------------------------------------------------------
__global__ void im2col_kernel(const float* __restrict__ x) {
    int g = blockIdx.x * blockDim.x + threadIdx.x;
    size_t idx0 = (size_t)g * 4;
    if (idx0 >= (size_t)NROWS * KDIM) return;
    int b = (int)(idx0 / PER_BATCH);
    int r = (int)(idx0 - (size_t)b * PER_BATCH);
    int f = r >> 10;
    int l = r & 1023;         // multiple of 4
    int y = l >> 5, x0 = l & 31;
    int c = f / 9;
    int kk = f - c * 9;
    int di = kk / 3;
    int dj = kk - di * 3;
    int iy = y + di - 1;
    const float* src = x + (((size_t)(b * 256 + c) * 32 + iy) << 5);
    uint32_t hw[2];
    #pragma unroll
    for (int pair = 0; pair < 2; pair++) {
        __half h[2];
        #pragma unroll
        for (int e = 0; e < 2; e++) {
            int ix = x0 + pair * 2 + e + dj - 1;
            float v = 0.0f;
            if ((unsigned)iy < 32u && (unsigned)ix < 32u) v = src[ix];
            h[e] = __float2half_rn(v);
        }
        hw[pair] = (uint32_t)__half_as_ushort(h[0]) |
                   ((uint32_t)__half_as_ushort(h[1]) << 16);
    }
    *(uint2*)(g_Ah + idx0) = make_uint2(hw[0], hw[1]);
}

// ---------------------------------------------------------------------------
// Kernel 3: fp16 mma.sync GEMM. CTA 128x256, 512 threads (16 warps, 64x32 warp
// tile), k-chunk 32, 4-stage cp.async pipeline, fp32 accum.
// ---------------------------------------------------------------------------
#define KCH 32
#define NCK (KDIM / KCH)      // 72
#define NSTG 4
#define LDS_STRIDE 40         // 32 + 8 pad (80B rows -> ldmatrix conflict-free)
#define SA (128 * LDS_STRIDE) // 5120 elems per A stage
#define SB (256 * LDS_STRIDE) // 10240 elems per B stage
#define OFF_AH 0
#define OFF_BH (NSTG * SA)                 // 20480
#define SMEM_ELEMS (NSTG * (SA + SB))      // 61440 elems
#define SMEM_BYTES (SMEM_ELEMS * 2)        // 122880 B

__device__ __forceinline__ uint32_t smem_u32(const void* p) {
    uint32_t a;
    asm("{ .reg .u64 t; cvta.to.shared.u64 t, %1; cvt.u32.u64 %0, t; }"
        : "=r"(a) : "l"(p));
    return a;
}
__device__ __forceinline__ void cpa16(uint32_t s, const void* g) {
    asm volatile("cp.async.cg.shared.global [%0], [%1], 16;" :: "r"(s), "l"(g));
}
#define CP_COMMIT()  asm volatile("cp.async.commit_group;" ::: "memory")
#define CP_WAIT(n)   asm volatile("cp.async.wait_group %0;" :: "n"(n) : "memory")

#define LDSM4(r0, r1, r2, r3, addr) \
    asm volatile("ldmatrix.sync.aligned.m8n8.x4.shared.b16 {%0,%1,%2,%3}, [%4];" \
                 : "=r"(r0), "=r"(r1), "=r"(r2), "=r"(r3) : "r"(addr))

#define MMA16816(d, a, b) \
    asm volatile("mma.sync.aligned.m16n8k16.row.col.f32.f16.f16.f32 " \
                 "{%0,%1,%2,%3}, {%4,%5,%6,%7}, {%8,%9}, {%0,%1,%2,%3};" \
                 : "+f"((d)[0]), "+f"((d)[1]), "+f"((d)[2]), "+f"((d)[3]) \
                 : "r"((a)[0]), "r"((a)[1]), "r"((a)[2]), "r"((a)[3]), \
                   "r"((b)[0]), "r"((b)[1]))

__global__ __launch_bounds__(512, 1) void gemm_kernel(float* __restrict__ out) {
    extern __shared__ __align__(16) __half sm[];
    const uint32_t sbase = smem_u32(sm);
    const int tid  = threadIdx.x;
    const int lane = tid & 31;
    const int wid  = tid >> 5;
    const int wm   = wid & 1;        // 2 m-groups of 64
    const int wn   = wid >> 1;       // 8 n-groups of 32
    const int bx   = blockIdx.x;     // 0..1 (256 cols)
    const int by   = blockIdx.y;     // 0..63 (128 rows)

    const __half* Ah = g_Ah + (size_t)(by * 128) * KDIM;
    const __half* Bh = g_Bh + (size_t)(bx * 256) * KDIM;

    // Per-thread load slots
    const int arow = tid >> 2, ac = tid & 3;              // A: 512 16B segs
    const size_t a_goff = (size_t)arow * KDIM + ac * 8;
    const uint32_t a_soff = (arow * LDS_STRIDE + ac * 8) * 2;
    const int brow0 = tid >> 2, bc = tid & 3;             // B: 1024 segs, 2/thread
    const size_t b_goff0 = (size_t)brow0 * KDIM + bc * 8;
    const size_t b_goff1 = (size_t)(brow0 + 128) * KDIM + bc * 8;
    const uint32_t b_soff0 = (brow0 * LDS_STRIDE + bc * 8) * 2;
    const uint32_t b_soff1 = ((brow0 + 128) * LDS_STRIDE + bc * 8) * 2;

    float acc[4][4][4];
    #pragma unroll
    for (int i = 0; i < 4; i++)
        #pragma unroll
        for (int j = 0; j < 4; j++)
            #pragma unroll
            for (int e = 0; e < 4; e++) acc[i][j][e] = 0.0f;

    const int a_lrow = (lane & 15);
    const int a_lcol = ((lane >> 4) & 1) * 8;
    const int b_lrow = ((lane >> 4) & 1) * 8 + (lane & 7);
    const int b_lcol = ((lane >> 3) & 1) * 8;

    auto load_chunk = [&](int ck, int stage) {
        const int k0 = ck * KCH;
        cpa16(sbase + (OFF_AH + stage * SA) * 2 + a_soff, Ah + a_goff + k0);
        uint32_t sh = sbase + (OFF_BH + stage * SB) * 2;
        cpa16(sh + b_soff0, Bh + b_goff0 + k0);
        cpa16(sh + b_soff1, Bh + b_goff1 + k0);
    };

    load_chunk(0, 0); CP_COMMIT();
    load_chunk(1, 1); CP_COMMIT();
    load_chunk(2, 2); CP_COMMIT();

    for (int ck = 0; ck < NCK; ck++) {
        const int stage = ck & 3;
        if (ck < NCK - 2)       { CP_WAIT(2); }
        else if (ck == NCK - 2) { CP_WAIT(1); }
        else                    { CP_WAIT(0); }
        __syncthreads();
        if (ck + 3 < NCK) { load_chunk(ck + 3, (ck + 3) & 3); CP_COMMIT(); }

        const uint32_t ah_base = sbase + (OFF_AH + stage * SA) * 2;
        const uint32_t bh_base = sbase + (OFF_BH + stage * SB) * 2;

        #pragma unroll
        for (int h = 0; h < 2; h++) {
            uint32_t ahr[4][4], bhr[4][2];
            #pragma unroll
            for (int mt = 0; mt < 4; mt++) {
                uint32_t off = ((wm * 64 + mt * 16 + a_lrow) * LDS_STRIDE
                                + h * 16 + a_lcol) * 2;
                LDSM4(ahr[mt][0], ahr[mt][1], ahr[mt][2], ahr[mt][3], ah_base + off);
            }
            #pragma unroll
            for (int nt2 = 0; nt2 < 2; nt2++) {
                uint32_t off = ((wn * 32 + nt2 * 16 + b_lrow) * LDS_STRIDE
                                + h * 16 + b_lcol) * 2;
                uint32_t r0, r1, r2, r3;
                LDSM4(r0, r1, r2, r3, bh_base + off);
                bhr[nt2 * 2][0] = r0; bhr[nt2 * 2][1] = r1;
                bhr[nt2 * 2 + 1][0] = r2; bhr[nt2 * 2 + 1][1] = r3;
            }
            #pragma unroll
            for (int mt = 0; mt < 4; mt++)
                #pragma unroll
                for (int nt = 0; nt < 4; nt++)
                    MMA16816(acc[mt][nt], ahr[mt], bhr[nt]);
        }
    }

    // Epilogue: C[R, j] -> out[(b*512 + j)*1024 + (R & 1023)]
    const int b     = by >> 3;
    const int lbase = (by & 7) * 128;
    #pragma unroll
    for (int mt = 0; mt < 4; mt++) {
        const int r0 = wm * 64 + mt * 16 + (lane >> 2);
        #pragma unroll
        for (int nt = 0; nt < 4; nt++) {
            const int j0 = bx * 256 + wn * 32 + nt * 8 + 2 * (lane & 3);
            float* o0 = out + (((size_t)(b * 512 + j0)) << 10) + lbase;
            float* o1 = out + (((size_t)(b * 512 + j0 + 1)) << 10) + lbase;
            o0[r0]     = acc[mt][nt][0];
            o1[r0]     = acc[mt][nt][1];
            o0[r0 + 8] = acc[mt][nt][2];
            o1[r0 + 8] = acc[mt][nt][3];
        }
    }
}

// Marker FIRST: shifts the ncu capture slot (previously landed on the 4th
// launch of the cycle) onto the GEMM.
__global__ void marker_kernel() {}

// ---------------------------------------------------------------------------
extern "C" void kernel_launch(void* const* d_in, const int* in_sizes, int n_in,
                              void* d_out, int out_size) {
    const float* x = (const float*)d_in[0];
    const float* w = (const float*)d_in[1];
    float* out = (float*)d_out;

    cudaFuncSetAttribute(gemm_kernel,
                         cudaFuncAttributeMaxDynamicSharedMemorySize, SMEM_BYTES);

    marker_kernel<<<1, 32>>>();
    build_wt_kernel<<<288, 256>>>(w);
    im2col_kernel<<<(NROWS * KDIM / 4 + 255) / 256, 256>>>(x);
    gemm_kernel<<<dim3(2, 64), 512, SMEM_BYTES>>>(out);
}